// round 3
// baseline (speedup 1.0000x reference)
#include <cuda_runtime.h>
#include <cstdint>

#define NN 50000
#define RR 16
#define HH 64
#define CC 16
#define EE 800000

typedef unsigned long long u64;

// packed fp32x2 FMA: d = a*b + d  (elementwise on {lo,hi}); bit-exact fp32
#define FMA2(d, a, b) asm("fma.rn.f32x2 %0, %1, %2, %0;" : "+l"(d) : "l"(a), "l"(b))
#define UNPACK2(lo, hi, v) asm("mov.b64 {%0, %1}, %2;" : "=f"(lo), "=f"(hi) : "l"(v))

// ---------------- device scratch (static; no allocation) ----------------
__device__ float g_Y[(size_t)NN * RR * HH];   // per-(node,relation) feature sums
__device__ int   g_cnt[NN * RR];              // edge counts per (dst, relation)
__device__ float g_inv[NN * RR];              // 1/cnt (0 if cnt==0)
__device__ float g_X1[(size_t)NN * HH];       // hidden layer activations

// ---------------- utility kernels ----------------
__global__ void zero_Y_k() {
    size_t i = (size_t)blockIdx.x * blockDim.x + threadIdx.x;
    if (i < (size_t)NN * RR * HH / 4)
        ((float4*)g_Y)[i] = make_float4(0.f, 0.f, 0.f, 0.f);
}

__global__ void zero_cnt_k() {
    int i = blockIdx.x * blockDim.x + threadIdx.x;
    if (i < NN * RR) g_cnt[i] = 0;
}

__global__ void count_k(const int* __restrict__ ei, const int* __restrict__ et) {
    int e = blockIdx.x * blockDim.x + threadIdx.x;
    if (e < EE) atomicAdd(&g_cnt[ei[EE + e] * RR + et[e]], 1);
}

__global__ void inv_k() {
    int i = blockIdx.x * blockDim.x + threadIdx.x;
    if (i < NN * RR) {
        int c = g_cnt[i];
        g_inv[i] = (c > 0) ? 1.0f / (float)c : 0.0f;
    }
}

// ---------------- edge scatter: Y[dst, type, :] += x[src, :] ----------------
template <bool USE_X1>
__global__ void scatter_t(const int* __restrict__ ei, const int* __restrict__ et,
                          const float4* __restrict__ xin) {
    unsigned t = blockIdx.x * blockDim.x + threadIdx.x;
    unsigned e = t >> 4;
    unsigned j = t & 15;
    if (e < EE) {
        const float4* x = USE_X1 ? (const float4*)g_X1 : xin;
        int src = ei[e];
        int dst = ei[EE + e];
        int r   = et[e];
        float4 v = x[(size_t)src * 16 + j];
        float* p = &g_Y[((size_t)dst * RR + r) * HH + j * 4];
        asm volatile("red.global.add.v4.f32 [%0], {%1,%2,%3,%4};"
                     :: "l"(__cvta_generic_to_global(p)),
                        "f"(v.x), "f"(v.y), "f"(v.z), "f"(v.w)
                     : "memory");
    }
}

// ---------------- layer 1 GEMM: X1 = relu( [Y_norm | x] @ [W1 ; root1] + b1 ) ----------------
// M=NN, K=1088 (34 chunks of 32), N=64. BM=128, BN=64, BK=32, 256 threads.
// Micro-tile 8 rows x 4 cols per thread, computed with fma.rn.f32x2.
// A tile stored DUPLICATED as float2{a,a} so no per-iteration packing is needed.
__global__ __launch_bounds__(256) void gemm1_k(const float* __restrict__ x,
                                               const float* __restrict__ W1,
                                               const float* __restrict__ root1,
                                               const float* __restrict__ b1) {
    __shared__ float2 As2[32][129];   // [k][node], duplicated pairs, padded
    __shared__ float  Bs[32][64];     // [k][n]
    int tid = threadIdx.x;
    int tx = tid & 15;        // output cols tx*4 .. tx*4+3
    int ty = tid >> 4;        // output rows ty*8 .. ty*8+7
    int v0 = blockIdx.x * 128;

    u64 acc[8][2] = {};

    for (int t = 0; t < 34; ++t) {
        // --- load B tile (32x64 floats = 512 float4; 2 per thread) ---
        const float4* Bsrc = (t < 32)
            ? (const float4*)(W1 + (size_t)(t >> 1) * 4096 + (size_t)(t & 1) * 32 * 64)
            : (const float4*)(root1 + (size_t)(t - 32) * 32 * 64);
        #pragma unroll
        for (int i = 0; i < 2; ++i) {
            int idx = tid + i * 256;
            int bk = idx >> 4, bn = idx & 15;
            float4 bv = Bsrc[bk * 16 + bn];
            *(float4*)&Bs[bk][bn * 4] = bv;
        }
        // --- load A tile (128 nodes x 32 k) with mean normalization, duplicated ---
        #pragma unroll
        for (int i = 0; i < 4; ++i) {
            int idx = tid + i * 256;          // float4 index 0..1023
            int node = idx >> 3;
            int kq   = idx & 7;
            int v = v0 + node;
            float4 av = make_float4(0.f, 0.f, 0.f, 0.f);
            float sc = 0.f;
            if (v < NN) {
                if (t < 32) {
                    int r = t >> 1;
                    av = *(const float4*)&g_Y[(size_t)v * 1024 + r * 64 + (t & 1) * 32 + kq * 4];
                    sc = g_inv[v * RR + r];
                } else {
                    av = *(const float4*)&x[(size_t)v * 64 + (t - 32) * 32 + kq * 4];
                    sc = 1.0f;
                }
            }
            int k0 = kq * 4;
            float fx = av.x * sc, fy = av.y * sc, fz = av.z * sc, fw = av.w * sc;
            As2[k0 + 0][node] = make_float2(fx, fx);
            As2[k0 + 1][node] = make_float2(fy, fy);
            As2[k0 + 2][node] = make_float2(fz, fz);
            As2[k0 + 3][node] = make_float2(fw, fw);
        }
        __syncthreads();
        // --- inner product: 16 FMA2 per k-step (32 MACs/thread/k) ---
        #pragma unroll
        for (int kk = 0; kk < 32; ++kk) {
            u64 a[8];
            #pragma unroll
            for (int i = 0; i < 8; ++i)
                a[i] = *(const u64*)&As2[kk][ty * 8 + i];
            ulonglong2 bv = *(const ulonglong2*)&Bs[kk][tx * 4];
            #pragma unroll
            for (int i = 0; i < 8; ++i) {
                FMA2(acc[i][0], a[i], bv.x);
                FMA2(acc[i][1], a[i], bv.y);
            }
        }
        __syncthreads();
    }

    // --- epilogue: + bias, relu, store hidden ---
    int c0 = tx * 4;
    float4 bias = make_float4(b1[c0], b1[c0 + 1], b1[c0 + 2], b1[c0 + 3]);
    #pragma unroll
    for (int i = 0; i < 8; ++i) {
        int v = v0 + ty * 8 + i;
        if (v < NN) {
            float o0, o1, o2, o3;
            UNPACK2(o0, o1, acc[i][0]);
            UNPACK2(o2, o3, acc[i][1]);
            float4 o;
            o.x = fmaxf(o0 + bias.x, 0.f);
            o.y = fmaxf(o1 + bias.y, 0.f);
            o.z = fmaxf(o2 + bias.z, 0.f);
            o.w = fmaxf(o3 + bias.w, 0.f);
            *(float4*)&g_X1[(size_t)v * 64 + c0] = o;
        }
    }
}

// ---------------- layer 2 GEMM: out = [Y_norm | X1] @ [W2 ; root2] + b2 ----------------
// M=NN, K=1088 (34 chunks of 32), N=16. BM=128, BN=16, BK=32, 128 threads.
// Micro-tile 8 rows x 2 cols per thread (8 FMA2 per k-step).
__global__ __launch_bounds__(128) void gemm2_k(const float* __restrict__ W2,
                                               const float* __restrict__ root2,
                                               const float* __restrict__ b2,
                                               float* __restrict__ out) {
    __shared__ float2 As2[32][129];   // [k][node], duplicated pairs
    __shared__ float  Bs[32][16];
    int tid = threadIdx.x;
    int tx = tid & 7;         // output cols tx*2, tx*2+1
    int ty = tid >> 3;        // output rows ty*8 .. ty*8+7
    int v0 = blockIdx.x * 128;

    u64 acc[8] = {};

    for (int t = 0; t < 34; ++t) {
        // --- load B tile (32x16 floats = 128 float4; 1 per thread) ---
        {
            const float4* Bsrc = (t < 32)
                ? (const float4*)(W2 + (size_t)(t >> 1) * 1024 + (size_t)(t & 1) * 32 * 16)
                : (const float4*)(root2 + (size_t)(t - 32) * 32 * 16);
            int bk = tid >> 2, bn = tid & 3;
            float4 bv = Bsrc[bk * 4 + bn];
            *(float4*)&Bs[bk][bn * 4] = bv;
        }
        // --- load A tile (128 nodes x 32 k), duplicated ---
        #pragma unroll
        for (int i = 0; i < 8; ++i) {
            int idx = tid + i * 128;          // float4 index 0..1023
            int node = idx >> 3;
            int kq   = idx & 7;
            int v = v0 + node;
            float4 av = make_float4(0.f, 0.f, 0.f, 0.f);
            float sc = 0.f;
            if (v < NN) {
                if (t < 32) {
                    int r = t >> 1;
                    av = *(const float4*)&g_Y[(size_t)v * 1024 + r * 64 + (t & 1) * 32 + kq * 4];
                    sc = g_inv[v * RR + r];
                } else {
                    av = *(const float4*)&g_X1[(size_t)v * 64 + (t - 32) * 32 + kq * 4];
                    sc = 1.0f;
                }
            }
            int k0 = kq * 4;
            float fx = av.x * sc, fy = av.y * sc, fz = av.z * sc, fw = av.w * sc;
            As2[k0 + 0][node] = make_float2(fx, fx);
            As2[k0 + 1][node] = make_float2(fy, fy);
            As2[k0 + 2][node] = make_float2(fz, fz);
            As2[k0 + 3][node] = make_float2(fw, fw);
        }
        __syncthreads();
        #pragma unroll
        for (int kk = 0; kk < 32; ++kk) {
            u64 a[8];
            #pragma unroll
            for (int i = 0; i < 8; ++i)
                a[i] = *(const u64*)&As2[kk][ty * 8 + i];
            u64 bv = *(const u64*)&Bs[kk][tx * 2];
            #pragma unroll
            for (int i = 0; i < 8; ++i)
                FMA2(acc[i], a[i], bv);
        }
        __syncthreads();
    }

    int c0 = tx * 2;
    float bx = b2[c0], by = b2[c0 + 1];
    #pragma unroll
    for (int i = 0; i < 8; ++i) {
        int v = v0 + ty * 8 + i;
        if (v < NN) {
            float o0, o1;
            UNPACK2(o0, o1, acc[i]);
            float2 o = make_float2(o0 + bx, o1 + by);
            *(float2*)&out[(size_t)v * 16 + c0] = o;
        }
    }
}

// ---------------- launch ----------------
extern "C" void kernel_launch(void* const* d_in, const int* in_sizes, int n_in,
                              void* d_out, int out_size) {
    const int*   ei    = (const int*)d_in[0];
    const int*   et    = (const int*)d_in[1];
    const float* x     = (const float*)d_in[2];
    const float* W1    = (const float*)d_in[3];
    const float* root1 = (const float*)d_in[4];
    const float* b1    = (const float*)d_in[5];
    const float* W2    = (const float*)d_in[6];
    const float* root2 = (const float*)d_in[7];
    const float* b2    = (const float*)d_in[8];
    float* out = (float*)d_out;

    (void)in_sizes; (void)n_in; (void)out_size;

    const int Z_Y_BLOCKS  = (int)(((size_t)NN * RR * HH / 4 + 255) / 256);
    const int SC_BLOCKS   = (int)(((size_t)EE * 16 + 255) / 256);

    // counts / inverse means (shared by both layers)
    zero_cnt_k<<<(NN * RR + 255) / 256, 256>>>();
    count_k<<<(EE + 255) / 256, 256>>>(ei, et);
    inv_k<<<(NN * RR + 255) / 256, 256>>>();

    // ---- layer 1 ----
    zero_Y_k<<<Z_Y_BLOCKS, 256>>>();
    scatter_t<false><<<SC_BLOCKS, 256>>>(ei, et, (const float4*)x);
    gemm1_k<<<(NN + 127) / 128, 256>>>(x, W1, root1, b1);

    // ---- layer 2 ----
    zero_Y_k<<<Z_Y_BLOCKS, 256>>>();
    scatter_t<true><<<SC_BLOCKS, 256>>>(ei, et, nullptr);
    gemm2_k<<<(NN + 127) / 128, 128>>>(W2, root2, b2, out);
}

// round 12
// speedup vs baseline: 1.6747x; 1.6747x over previous
#include <cuda_runtime.h>
#include <cuda_bf16.h>
#include <cstdint>

#define NN 50000
#define RR 16
#define HH 64
#define CC 16
#define EE 800000

typedef unsigned int u32;
typedef unsigned long long u64;

// ---------------- device scratch (static; no allocation) ----------------
__device__ float g_Y[(size_t)NN * RR * HH];   // per-(node,relation) feature sums
__device__ int   g_cnt[NN * RR];              // edge counts per (dst, relation)
__device__ float g_inv[NN * RR];              // 1/cnt (0 if cnt==0)
__device__ float g_X1[(size_t)NN * HH];       // hidden layer activations

__device__ __forceinline__ u32 smem_u32(const void* p) {
    u32 a;
    asm("{ .reg .u64 t; cvta.to.shared.u64 t, %1; cvt.u32.u64 %0, t; }" : "=r"(a) : "l"(p));
    return a;
}

// ldmatrix x4 (sm_75+; compiles at plain sm_103)
__device__ __forceinline__ void ldm4(u32* d, u32 addr) {
    asm volatile("ldmatrix.sync.aligned.m8n8.x4.shared.b16 {%0,%1,%2,%3}, [%4];"
                 : "=r"(d[0]), "=r"(d[1]), "=r"(d[2]), "=r"(d[3]) : "r"(addr));
}

// classic HMMA bf16 -> f32 (sm_80+)
__device__ __forceinline__ void mma16816(float* d, const u32* a, u32 b0, u32 b1) {
    asm volatile("mma.sync.aligned.m16n8k16.row.col.f32.bf16.bf16.f32 "
                 "{%0,%1,%2,%3}, {%4,%5,%6,%7}, {%8,%9}, {%0,%1,%2,%3};"
                 : "+f"(d[0]), "+f"(d[1]), "+f"(d[2]), "+f"(d[3])
                 : "r"(a[0]), "r"(a[1]), "r"(a[2]), "r"(a[3]), "r"(b0), "r"(b1));
}

// ---------------- utility kernels ----------------
__global__ void zero_Y_k() {
    size_t i = (size_t)blockIdx.x * blockDim.x + threadIdx.x;
    if (i < (size_t)NN * RR * HH / 4)
        ((float4*)g_Y)[i] = make_float4(0.f, 0.f, 0.f, 0.f);
}

__global__ void zero_cnt_k() {
    int i = blockIdx.x * blockDim.x + threadIdx.x;
    if (i < NN * RR) g_cnt[i] = 0;
}

__global__ void count_k(const int* __restrict__ ei, const int* __restrict__ et) {
    int e = blockIdx.x * blockDim.x + threadIdx.x;
    if (e < EE) atomicAdd(&g_cnt[ei[EE + e] * RR + et[e]], 1);
}

__global__ void inv_k() {
    int i = blockIdx.x * blockDim.x + threadIdx.x;
    if (i < NN * RR) {
        int c = g_cnt[i];
        g_inv[i] = (c > 0) ? 1.0f / (float)c : 0.0f;
    }
}

// ---------------- edge scatter: Y[dst, type, :] += x[src, :] ----------------
template <bool USE_X1>
__global__ void scatter_t(const int* __restrict__ ei, const int* __restrict__ et,
                          const float4* __restrict__ xin) {
    unsigned t = blockIdx.x * blockDim.x + threadIdx.x;
    unsigned e = t >> 4;
    unsigned j = t & 15;
    if (e < EE) {
        const float4* x = USE_X1 ? (const float4*)g_X1 : xin;
        int src = ei[e];
        int dst = ei[EE + e];
        int r   = et[e];
        float4 v = x[(size_t)src * 16 + j];
        float* p = &g_Y[((size_t)dst * RR + r) * HH + j * 4];
        asm volatile("red.global.add.v4.f32 [%0], {%1,%2,%3,%4};"
                     :: "l"(__cvta_generic_to_global(p)),
                        "f"(v.x), "f"(v.y), "f"(v.z), "f"(v.w)
                     : "memory");
    }
}

// ---------------- HMMA GEMM (both layers) ----------------
// out = maybe_relu( [Y_norm | root_input] @ [W ; rootW] + bias )
// root_input = xin (layer 1) or g_X1 (layer 2, USE_X1).
// Output target: g_X1 (device-side symbol, OUT_X1) or outp (harness out).
// M=NN (BM=128, 8 warps x 16 rows), N=OUTD, K=1088 (17 chunks of 64).
// Split-bf16: D += Ah*Bh + Al*Bh + Ah*Bl, fp32 accumulation (residual ~1.6e-5).
template <int OUTD, bool RELU, bool USE_X1, bool OUT_X1>
__global__ __launch_bounds__(256) void gemm_mma(const float* __restrict__ xin,
                                                const float* __restrict__ W,
                                                const float* __restrict__ rootW,
                                                const float* __restrict__ bias,
                                                float* __restrict__ outp) {
    constexpr int AP = 72;                 // bf16 pitch: 144B rows, conflict-free ldmatrix
    extern __shared__ __nv_bfloat16 sm[];
    __nv_bfloat16* Ah = sm;
    __nv_bfloat16* Al = Ah + 128 * AP;
    __nv_bfloat16* Bh = Al + 128 * AP;
    __nv_bfloat16* Bl = Bh + OUTD * AP;

    int tid = threadIdx.x;
    int wid = tid >> 5, lane = tid & 31;
    int g = lane >> 3, r = lane & 7;
    int v0 = blockIdx.x * 128;

    u32 sb = smem_u32(sm);
    // A frag rows: m = wid*16 + (g&1)*8 + r ; cols: (g>>1)*8 (+k0 per step)
    u32 ah_base = sb + ((u32)((wid * 16 + (g & 1) * 8 + r) * AP + (g >> 1) * 8)) * 2;
    u32 al_base = ah_base + 128 * AP * 2;
    // B frag rows: n = (g>>1)*8 + r ; cols: (g&1)*8 (+k0 per step)
    u32 bh_base = sb + 256 * AP * 2 + ((u32)(((g >> 1) * 8 + r) * AP + (g & 1) * 8)) * 2;
    u32 bl_base = bh_base + OUTD * AP * 2;

    float acc[OUTD / 8][4];
    #pragma unroll
    for (int i = 0; i < OUTD / 8; ++i)
        #pragma unroll
        for (int j = 0; j < 4; ++j) acc[i][j] = 0.f;

    for (int t = 0; t < 17; ++t) {
        // ---- A tile prep: 128 nodes x 64 k, fp32*scale -> (hi, lo) bf16 ----
        #pragma unroll
        for (int i = 0; i < 8; ++i) {
            int idx = tid + i * 256;          // float4 units 0..2047
            int node = idx >> 4, kq = idx & 15;
            int v = v0 + node;
            float4 av = make_float4(0.f, 0.f, 0.f, 0.f);
            float sc = 0.f;
            if (v < NN) {
                if (t < 16) {
                    av = *(const float4*)&g_Y[(size_t)v * 1024 + t * 64 + kq * 4];
                    sc = g_inv[v * RR + t];
                } else {
                    const float* rsrc = USE_X1 ? g_X1 : xin;
                    av = *(const float4*)&rsrc[(size_t)v * 64 + kq * 4];
                    sc = 1.0f;
                }
            }
            float f[4] = {av.x * sc, av.y * sc, av.z * sc, av.w * sc};
            u32 hw[2], lw[2];
            #pragma unroll
            for (int j = 0; j < 2; ++j) {
                __nv_bfloat16 h0 = __float2bfloat16(f[j * 2]);
                __nv_bfloat16 h1 = __float2bfloat16(f[j * 2 + 1]);
                __nv_bfloat162 hp; hp.x = h0; hp.y = h1;
                hw[j] = *(u32*)&hp;
                __nv_bfloat162 lp;
                lp.x = __float2bfloat16(f[j * 2]     - __bfloat162float(h0));
                lp.y = __float2bfloat16(f[j * 2 + 1] - __bfloat162float(h1));
                lw[j] = *(u32*)&lp;
            }
            int o = node * AP + kq * 4;
            *(uint2*)&Ah[o] = make_uint2(hw[0], hw[1]);
            *(uint2*)&Al[o] = make_uint2(lw[0], lw[1]);
        }
        // ---- B tile prep: transpose [64 k][OUTD n] fp32 -> Bs[n][k] (hi, lo) ----
        {
            const float4* Bsrc = (t < 16) ? (const float4*)(W + (size_t)t * 64 * OUTD)
                                          : (const float4*)rootW;
            constexpr int NF4 = 64 * OUTD / 4;
            #pragma unroll
            for (int i = 0; i < NF4 / 256; ++i) {
                int idx = tid + i * 256;
                int k = idx / (OUTD / 4), nq = idx % (OUTD / 4);
                float4 w4 = Bsrc[idx];
                float f[4] = {w4.x, w4.y, w4.z, w4.w};
                #pragma unroll
                for (int j = 0; j < 4; ++j) {
                    int n = nq * 4 + j;
                    __nv_bfloat16 h = __float2bfloat16(f[j]);
                    Bh[n * AP + k] = h;
                    Bl[n * AP + k] = __float2bfloat16(f[j] - __bfloat162float(h));
                }
            }
        }
        __syncthreads();
        // ---- MMA: 4 k-steps x (OUTD/16) n-blocks x 3 split terms ----
        #pragma unroll
        for (int ks = 0; ks < 4; ++ks) {
            u32 ah[4], al[4];
            ldm4(ah, ah_base + ks * 32);
            ldm4(al, al_base + ks * 32);
            #pragma unroll
            for (int nb = 0; nb < OUTD / 16; ++nb) {
                u32 bh[4], bl[4];
                ldm4(bh, bh_base + ks * 32 + nb * (16 * AP * 2));
                ldm4(bl, bl_base + ks * 32 + nb * (16 * AP * 2));
                mma16816(acc[nb * 2],     ah, bh[0], bh[1]);
                mma16816(acc[nb * 2 + 1], ah, bh[2], bh[3]);
                mma16816(acc[nb * 2],     al, bh[0], bh[1]);
                mma16816(acc[nb * 2 + 1], al, bh[2], bh[3]);
                mma16816(acc[nb * 2],     ah, bl[0], bl[1]);
                mma16816(acc[nb * 2 + 1], ah, bl[2], bl[3]);
            }
        }
        __syncthreads();
    }

    // ---- epilogue: bias (+relu), direct fragment store ----
    float* dst = OUT_X1 ? g_X1 : outp;     // device-side symbol reference (ATS pitfall!)
    int row0 = v0 + wid * 16 + (lane >> 2);
    int colb = (lane & 3) * 2;
    #pragma unroll
    for (int ns = 0; ns < OUTD / 8; ++ns) {
        int col = ns * 8 + colb;
        float bx = bias[col], by = bias[col + 1];
        float o0 = acc[ns][0] + bx, o1 = acc[ns][1] + by;
        float o2 = acc[ns][2] + bx, o3 = acc[ns][3] + by;
        if (RELU) {
            o0 = fmaxf(o0, 0.f); o1 = fmaxf(o1, 0.f);
            o2 = fmaxf(o2, 0.f); o3 = fmaxf(o3, 0.f);
        }
        if (row0 < NN)
            *(float2*)&dst[(size_t)row0 * OUTD + col] = make_float2(o0, o1);
        if (row0 + 8 < NN)
            *(float2*)&dst[(size_t)(row0 + 8) * OUTD + col] = make_float2(o2, o3);
    }
}

// ---------------- launch ----------------
extern "C" void kernel_launch(void* const* d_in, const int* in_sizes, int n_in,
                              void* d_out, int out_size) {
    const int*   ei    = (const int*)d_in[0];
    const int*   et    = (const int*)d_in[1];
    const float* x     = (const float*)d_in[2];
    const float* W1    = (const float*)d_in[3];
    const float* root1 = (const float*)d_in[4];
    const float* b1    = (const float*)d_in[5];
    const float* W2    = (const float*)d_in[6];
    const float* root2 = (const float*)d_in[7];
    const float* b2    = (const float*)d_in[8];
    float* out = (float*)d_out;

    (void)in_sizes; (void)n_in; (void)out_size;

    constexpr int AP = 72;
    const int SMEM1 = (256 + 128) * AP * 2;   // 55296 B
    const int SMEM2 = (256 + 32) * AP * 2;    // 41472 B
    cudaFuncSetAttribute(gemm_mma<64, true, false, true>,
                         cudaFuncAttributeMaxDynamicSharedMemorySize, SMEM1);
    cudaFuncSetAttribute(gemm_mma<16, false, true, false>,
                         cudaFuncAttributeMaxDynamicSharedMemorySize, SMEM2);

    const int Z_Y_BLOCKS = (int)(((size_t)NN * RR * HH / 4 + 255) / 256);
    const int SC_BLOCKS  = (int)(((size_t)EE * 16 + 255) / 256);
    const int GB         = (NN + 127) / 128;

    // counts / inverse means (shared by both layers)
    zero_cnt_k<<<(NN * RR + 255) / 256, 256>>>();
    count_k<<<(EE + 255) / 256, 256>>>(ei, et);
    inv_k<<<(NN * RR + 255) / 256, 256>>>();

    // ---- layer 1 ----
    zero_Y_k<<<Z_Y_BLOCKS, 256>>>();
    scatter_t<false><<<SC_BLOCKS, 256>>>(ei, et, (const float4*)x);
    gemm_mma<64, true, false, true><<<GB, 256, SMEM1>>>(x, W1, root1, b1, nullptr);

    // ---- layer 2 ----
    zero_Y_k<<<Z_Y_BLOCKS, 256>>>();
    scatter_t<true><<<SC_BLOCKS, 256>>>(ei, et, nullptr);
    gemm_mma<16, false, true, false><<<GB, 256, SMEM2>>>(nullptr, W2, root2, b2, out);
}

// round 14
// speedup vs baseline: 2.3427x; 1.3989x over previous
#include <cuda_runtime.h>
#include <cuda_bf16.h>
#include <cuda_fp16.h>
#include <cstdint>

#define NN 50000
#define RR 16
#define HH 64
#define CC 16
#define EE 800000

typedef unsigned int u32;
typedef unsigned long long u64;

// ---------------- device scratch (static; no allocation) ----------------
__device__ __half g_Yh[(size_t)NN * RR * HH];  // per-(node,relation) sums, fp16, 102.4 MB (L2-resident)
__device__ int    g_cnt[NN * RR];              // edge counts per (dst, relation)
__device__ float  g_inv[NN * RR];              // 1/cnt (0 if cnt==0)
__device__ float  g_X1[(size_t)NN * HH];       // hidden layer activations (fp32)

__device__ __forceinline__ u32 smem_u32(const void* p) {
    u32 a;
    asm("{ .reg .u64 t; cvta.to.shared.u64 t, %1; cvt.u32.u64 %0, t; }" : "=r"(a) : "l"(p));
    return a;
}

// ldmatrix x4 (sm_75+; compiles at plain sm_103)
__device__ __forceinline__ void ldm4(u32* d, u32 addr) {
    asm volatile("ldmatrix.sync.aligned.m8n8.x4.shared.b16 {%0,%1,%2,%3}, [%4];"
                 : "=r"(d[0]), "=r"(d[1]), "=r"(d[2]), "=r"(d[3]) : "r"(addr));
}

// classic HMMA bf16 -> f32 (sm_80+)
__device__ __forceinline__ void mma16816(float* d, const u32* a, u32 b0, u32 b1) {
    asm volatile("mma.sync.aligned.m16n8k16.row.col.f32.bf16.bf16.f32 "
                 "{%0,%1,%2,%3}, {%4,%5,%6,%7}, {%8,%9}, {%0,%1,%2,%3};"
                 : "+f"(d[0]), "+f"(d[1]), "+f"(d[2]), "+f"(d[3])
                 : "r"(a[0]), "r"(a[1]), "r"(a[2]), "r"(a[3]), "r"(b0), "r"(b1));
}

// ---------------- utility kernels ----------------
__global__ void zero_Y_k() {   // zeroes fp16 Y (102.4 MB) as float4 stores
    size_t i = (size_t)blockIdx.x * blockDim.x + threadIdx.x;
    if (i < (size_t)NN * RR * HH * 2 / 16)
        ((float4*)g_Yh)[i] = make_float4(0.f, 0.f, 0.f, 0.f);
}

__global__ void zero_cnt_k() {
    int i = blockIdx.x * blockDim.x + threadIdx.x;
    if (i < NN * RR) g_cnt[i] = 0;
}

__global__ void inv_k() {
    int i = blockIdx.x * blockDim.x + threadIdx.x;
    if (i < NN * RR) {
        int c = g_cnt[i];
        g_inv[i] = (c > 0) ? 1.0f / (float)c : 0.0f;
    }
}

// ---------------- edge scatter: Yh[dst, type, :] += fp16(x[src, :]) ----------------
// 8 lanes per edge, 16 B (8 halves) per lane via red.v4.f16x2.
// Lane 0 also counts the edge (layer 1 only) — replaces count_k.
template <bool USE_X1, bool COUNT>
__global__ void scatter_h(const int* __restrict__ ei, const int* __restrict__ et,
                          const float4* __restrict__ xin) {
    unsigned t = blockIdx.x * blockDim.x + threadIdx.x;
    unsigned e = t >> 3;
    unsigned j = t & 7;
    if (e < EE) {
        const float4* x = USE_X1 ? (const float4*)g_X1 : xin;
        int src = ei[e];
        int dst = ei[EE + e];
        int r   = et[e];
        float4 a = x[(size_t)src * 16 + j * 2];
        float4 b = x[(size_t)src * 16 + j * 2 + 1];
        __half2 h0 = __floats2half2_rn(a.x, a.y);
        __half2 h1 = __floats2half2_rn(a.z, a.w);
        __half2 h2 = __floats2half2_rn(b.x, b.y);
        __half2 h3 = __floats2half2_rn(b.z, b.w);
        __half* p = &g_Yh[((size_t)dst * RR + r) * HH + j * 8];
        asm volatile("red.global.add.noftz.v4.f16x2 [%0], {%1,%2,%3,%4};"
                     :: "l"(__cvta_generic_to_global(p)),
                        "r"(*(u32*)&h0), "r"(*(u32*)&h1), "r"(*(u32*)&h2), "r"(*(u32*)&h3)
                     : "memory");
        if (COUNT && j == 0) atomicAdd(&g_cnt[dst * RR + r], 1);
    }
}

// ---------------- HMMA GEMM (both layers) ----------------
// out = maybe_relu( [Yh_norm | root_input] @ [W ; rootW] + bias )
// root_input = xin (layer 1) or g_X1 (layer 2, USE_X1); output: g_X1 (OUT_X1) or outp.
// M=NN (BM=128, 8 warps x 16 rows), N=OUTD, K=1088 (17 chunks of 64).
// Split-bf16: D += Ah*Bh + Al*Bh + Ah*Bl (fp16->hi/lo split is EXACT).
template <int OUTD, bool RELU, bool USE_X1, bool OUT_X1>
__global__ __launch_bounds__(256) void gemm_mma(const float* __restrict__ xin,
                                                const float* __restrict__ W,
                                                const float* __restrict__ rootW,
                                                const float* __restrict__ bias,
                                                float* __restrict__ outp) {
    constexpr int AP = 72;                 // bf16 pitch: 144B rows, conflict-free ldmatrix
    extern __shared__ __nv_bfloat16 sm[];
    __nv_bfloat16* Ah = sm;
    __nv_bfloat16* Al = Ah + 128 * AP;
    __nv_bfloat16* Bh = Al + 128 * AP;
    __nv_bfloat16* Bl = Bh + OUTD * AP;

    int tid = threadIdx.x;
    int wid = tid >> 5, lane = tid & 31;
    int g = lane >> 3, r = lane & 7;
    int v0 = blockIdx.x * 128;

    u32 sb = smem_u32(sm);
    u32 ah_base = sb + ((u32)((wid * 16 + (g & 1) * 8 + r) * AP + (g >> 1) * 8)) * 2;
    u32 al_base = ah_base + 128 * AP * 2;
    u32 bh_base = sb + 256 * AP * 2 + ((u32)(((g >> 1) * 8 + r) * AP + (g & 1) * 8)) * 2;
    u32 bl_base = bh_base + OUTD * AP * 2;

    float acc[OUTD / 8][4];
    #pragma unroll
    for (int i = 0; i < OUTD / 8; ++i)
        #pragma unroll
        for (int j = 0; j < 4; ++j) acc[i][j] = 0.f;

    for (int t = 0; t < 17; ++t) {
        // ---- A tile prep ----
        if (t < 16) {
            // fp16 Y path: 1024 uint4 units (8 halves each), 4 iters
            #pragma unroll
            for (int i = 0; i < 4; ++i) {
                int idx = tid + i * 256;
                int node = idx >> 3, kq = idx & 7;
                int v = v0 + node;
                uint4 yv = make_uint4(0, 0, 0, 0);
                float sc = 0.f;
                if (v < NN) {
                    yv = *(const uint4*)&g_Yh[(size_t)v * 1024 + t * 64 + kq * 8];
                    sc = g_inv[v * RR + t];
                }
                u32 yw[4] = {yv.x, yv.y, yv.z, yv.w};
                u32 hw[4], lw[4];
                #pragma unroll
                for (int q = 0; q < 4; ++q) {
                    __half2 hp = *(__half2*)&yw[q];
                    float f0 = __low2float(hp)  * sc;
                    float f1 = __high2float(hp) * sc;
                    __nv_bfloat16 h0 = __float2bfloat16(f0);
                    __nv_bfloat16 h1 = __float2bfloat16(f1);
                    __nv_bfloat162 hb; hb.x = h0; hb.y = h1;
                    hw[q] = *(u32*)&hb;
                    __nv_bfloat162 lb;
                    lb.x = __float2bfloat16(f0 - __bfloat162float(h0));
                    lb.y = __float2bfloat16(f1 - __bfloat162float(h1));
                    lw[q] = *(u32*)&lb;
                }
                int o = node * AP + kq * 8;
                *(uint4*)&Ah[o] = make_uint4(hw[0], hw[1], hw[2], hw[3]);
                *(uint4*)&Al[o] = make_uint4(lw[0], lw[1], lw[2], lw[3]);
            }
        } else {
            // root chunk: fp32 input, 2048 float4 units, 8 iters
            #pragma unroll
            for (int i = 0; i < 8; ++i) {
                int idx = tid + i * 256;
                int node = idx >> 4, kq = idx & 15;
                int v = v0 + node;
                float4 av = make_float4(0.f, 0.f, 0.f, 0.f);
                if (v < NN) {
                    const float* rsrc = USE_X1 ? g_X1 : xin;
                    av = *(const float4*)&rsrc[(size_t)v * 64 + kq * 4];
                }
                float f[4] = {av.x, av.y, av.z, av.w};
                u32 hw[2], lw[2];
                #pragma unroll
                for (int q = 0; q < 2; ++q) {
                    __nv_bfloat16 h0 = __float2bfloat16(f[q * 2]);
                    __nv_bfloat16 h1 = __float2bfloat16(f[q * 2 + 1]);
                    __nv_bfloat162 hb; hb.x = h0; hb.y = h1;
                    hw[q] = *(u32*)&hb;
                    __nv_bfloat162 lb;
                    lb.x = __float2bfloat16(f[q * 2]     - __bfloat162float(h0));
                    lb.y = __float2bfloat16(f[q * 2 + 1] - __bfloat162float(h1));
                    lw[q] = *(u32*)&lb;
                }
                int o = node * AP + kq * 4;
                *(uint2*)&Ah[o] = make_uint2(hw[0], hw[1]);
                *(uint2*)&Al[o] = make_uint2(lw[0], lw[1]);
            }
        }
        // ---- B tile prep: transpose [64 k][OUTD n] fp32 -> Bs[n][k] (hi, lo) ----
        {
            const float4* Bsrc = (t < 16) ? (const float4*)(W + (size_t)t * 64 * OUTD)
                                          : (const float4*)rootW;
            constexpr int NF4 = 64 * OUTD / 4;
            #pragma unroll
            for (int i = 0; i < NF4 / 256; ++i) {
                int idx = tid + i * 256;
                int k = idx / (OUTD / 4), nq = idx % (OUTD / 4);
                float4 w4 = Bsrc[idx];
                float f[4] = {w4.x, w4.y, w4.z, w4.w};
                #pragma unroll
                for (int j = 0; j < 4; ++j) {
                    int n = nq * 4 + j;
                    __nv_bfloat16 h = __float2bfloat16(f[j]);
                    Bh[n * AP + k] = h;
                    Bl[n * AP + k] = __float2bfloat16(f[j] - __bfloat162float(h));
                }
            }
        }
        __syncthreads();
        // ---- MMA: 4 k-steps x (OUTD/16) n-blocks x 3 split terms ----
        #pragma unroll
        for (int ks = 0; ks < 4; ++ks) {
            u32 ah[4], al[4];
            ldm4(ah, ah_base + ks * 32);
            ldm4(al, al_base + ks * 32);
            #pragma unroll
            for (int nb = 0; nb < OUTD / 16; ++nb) {
                u32 bh[4], bl[4];
                ldm4(bh, bh_base + ks * 32 + nb * (16 * AP * 2));
                ldm4(bl, bl_base + ks * 32 + nb * (16 * AP * 2));
                mma16816(acc[nb * 2],     ah, bh[0], bh[1]);
                mma16816(acc[nb * 2 + 1], ah, bh[2], bh[3]);
                mma16816(acc[nb * 2],     al, bh[0], bh[1]);
                mma16816(acc[nb * 2 + 1], al, bh[2], bh[3]);
                mma16816(acc[nb * 2],     ah, bl[0], bl[1]);
                mma16816(acc[nb * 2 + 1], ah, bl[2], bl[3]);
            }
        }
        __syncthreads();
    }

    // ---- epilogue: bias (+relu), direct fragment store ----
    float* dst = OUT_X1 ? g_X1 : outp;     // device-side symbol reference (ATS pitfall!)
    int row0 = v0 + wid * 16 + (lane >> 2);
    int colb = (lane & 3) * 2;
    #pragma unroll
    for (int ns = 0; ns < OUTD / 8; ++ns) {
        int col = ns * 8 + colb;
        float bx = bias[col], by = bias[col + 1];
        float o0 = acc[ns][0] + bx, o1 = acc[ns][1] + by;
        float o2 = acc[ns][2] + bx, o3 = acc[ns][3] + by;
        if (RELU) {
            o0 = fmaxf(o0, 0.f); o1 = fmaxf(o1, 0.f);
            o2 = fmaxf(o2, 0.f); o3 = fmaxf(o3, 0.f);
        }
        if (row0 < NN)
            *(float2*)&dst[(size_t)row0 * OUTD + col] = make_float2(o0, o1);
        if (row0 + 8 < NN)
            *(float2*)&dst[(size_t)(row0 + 8) * OUTD + col] = make_float2(o2, o3);
    }
}

// ---------------- launch ----------------
extern "C" void kernel_launch(void* const* d_in, const int* in_sizes, int n_in,
                              void* d_out, int out_size) {
    const int*   ei    = (const int*)d_in[0];
    const int*   et    = (const int*)d_in[1];
    const float* x     = (const float*)d_in[2];
    const float* W1    = (const float*)d_in[3];
    const float* root1 = (const float*)d_in[4];
    const float* b1    = (const float*)d_in[5];
    const float* W2    = (const float*)d_in[6];
    const float* root2 = (const float*)d_in[7];
    const float* b2    = (const float*)d_in[8];
    float* out = (float*)d_out;

    (void)in_sizes; (void)n_in; (void)out_size;

    constexpr int AP = 72;
    const int SMEM1 = (256 + 128) * AP * 2;   // 55296 B
    const int SMEM2 = (256 + 32) * AP * 2;    // 41472 B
    cudaFuncSetAttribute(gemm_mma<64, true, false, true>,
                         cudaFuncAttributeMaxDynamicSharedMemorySize, SMEM1);
    cudaFuncSetAttribute(gemm_mma<16, false, true, false>,
                         cudaFuncAttributeMaxDynamicSharedMemorySize, SMEM2);

    const int Z_Y_BLOCKS = (int)(((size_t)NN * RR * HH * 2 / 16 + 255) / 256); // 25000
    const int SC_BLOCKS  = (int)(((size_t)EE * 8 + 255) / 256);                // 25000
    const int GB         = (NN + 127) / 128;

    // ---- layer 1 ----
    zero_cnt_k<<<(NN * RR + 255) / 256, 256>>>();
    zero_Y_k<<<Z_Y_BLOCKS, 256>>>();
    scatter_h<false, true><<<SC_BLOCKS, 256>>>(ei, et, (const float4*)x);  // + counts
    inv_k<<<(NN * RR + 255) / 256, 256>>>();
    gemm_mma<64, true, false, true><<<GB, 256, SMEM1>>>(x, W1, root1, b1, nullptr);

    // ---- layer 2 ----
    zero_Y_k<<<Z_Y_BLOCKS, 256>>>();
    scatter_h<true, false><<<SC_BLOCKS, 256>>>(ei, et, nullptr);
    gemm_mma<16, false, true, false><<<GB, 256, SMEM2>>>(nullptr, W2, root2, b2, out);
}

// round 15
// speedup vs baseline: 2.8512x; 1.2171x over previous
#include <cuda_runtime.h>
#include <cuda_fp16.h>
#include <cstdint>

#define NN 50000
#define RR 16
#define HH 64
#define CC 16
#define EE 800000

typedef unsigned int u32;
typedef unsigned long long u64;

// ---------------- device scratch (static; no allocation) ----------------
__device__ __half g_Yh[(size_t)NN * RR * HH];  // per-(node,relation) sums, fp16, 102.4 MB (L2-resident)
__device__ int    g_cnt[NN * RR];              // edge counts per (dst, relation)
__device__ float  g_inv[NN * RR];              // 1/cnt (0 if cnt==0)
__device__ float  g_X1[(size_t)NN * HH];       // hidden layer activations (fp32)

__device__ __forceinline__ u32 smem_u32(const void* p) {
    u32 a;
    asm("{ .reg .u64 t; cvta.to.shared.u64 t, %1; cvt.u32.u64 %0, t; }" : "=r"(a) : "l"(p));
    return a;
}

// ldmatrix x4 (sm_75+; compiles at plain sm_103)
__device__ __forceinline__ void ldm4(u32* d, u32 addr) {
    asm volatile("ldmatrix.sync.aligned.m8n8.x4.shared.b16 {%0,%1,%2,%3}, [%4];"
                 : "=r"(d[0]), "=r"(d[1]), "=r"(d[2]), "=r"(d[3]) : "r"(addr));
}

// classic HMMA fp16 -> f32 accumulate (sm_80+; f16 x f16 products exact in f32)
__device__ __forceinline__ void mma16816(float* d, const u32* a, u32 b0, u32 b1) {
    asm volatile("mma.sync.aligned.m16n8k16.row.col.f32.f16.f16.f32 "
                 "{%0,%1,%2,%3}, {%4,%5,%6,%7}, {%8,%9}, {%0,%1,%2,%3};"
                 : "+f"(d[0]), "+f"(d[1]), "+f"(d[2]), "+f"(d[3])
                 : "r"(a[0]), "r"(a[1]), "r"(a[2]), "r"(a[3]), "r"(b0), "r"(b1));
}

// ---------------- utility kernels ----------------
__global__ void zero_Y_k() {   // zeroes fp16 Y (102.4 MB) as float4 stores
    size_t i = (size_t)blockIdx.x * blockDim.x + threadIdx.x;
    if (i < (size_t)NN * RR * HH * 2 / 16)
        ((float4*)g_Yh)[i] = make_float4(0.f, 0.f, 0.f, 0.f);
}

__global__ void zero_cnt_k() {
    int i = blockIdx.x * blockDim.x + threadIdx.x;
    if (i < NN * RR) g_cnt[i] = 0;
}

__global__ void inv_k() {
    int i = blockIdx.x * blockDim.x + threadIdx.x;
    if (i < NN * RR) {
        int c = g_cnt[i];
        g_inv[i] = (c > 0) ? 1.0f / (float)c : 0.0f;
    }
}

// ---------------- edge scatter: Yh[dst, type, :] += fp16(x[src, :]) ----------------
// 8 lanes per edge, 16 B (8 halves) per lane via red.v4.f16x2.
// Lane 0 also counts the edge (layer 1 only).
template <bool USE_X1, bool COUNT>
__global__ void scatter_h(const int* __restrict__ ei, const int* __restrict__ et,
                          const float4* __restrict__ xin) {
    unsigned t = blockIdx.x * blockDim.x + threadIdx.x;
    unsigned e = t >> 3;
    unsigned j = t & 7;
    if (e < EE) {
        const float4* x = USE_X1 ? (const float4*)g_X1 : xin;
        int src = ei[e];
        int dst = ei[EE + e];
        int r   = et[e];
        float4 a = x[(size_t)src * 16 + j * 2];
        float4 b = x[(size_t)src * 16 + j * 2 + 1];
        __half2 h0 = __floats2half2_rn(a.x, a.y);
        __half2 h1 = __floats2half2_rn(a.z, a.w);
        __half2 h2 = __floats2half2_rn(b.x, b.y);
        __half2 h3 = __floats2half2_rn(b.z, b.w);
        __half* p = &g_Yh[((size_t)dst * RR + r) * HH + j * 8];
        asm volatile("red.global.add.noftz.v4.f16x2 [%0], {%1,%2,%3,%4};"
                     :: "l"(__cvta_generic_to_global(p)),
                        "r"(*(u32*)&h0), "r"(*(u32*)&h1), "r"(*(u32*)&h2), "r"(*(u32*)&h3)
                     : "memory");
        if (COUNT && j == 0) atomicAdd(&g_cnt[dst * RR + r], 1);
    }
}

// ---------------- HMMA GEMM (both layers) ----------------
// out = maybe_relu( [Yh_norm | root_input] @ [W ; rootW] + bias )
// A: single fp16 (mean rounded ONCE in fp32 then packed). B: f16/f16 split
// (Wh + Wl, ~2^-22 error). D += A*Wh + A*Wl, fp32 accumulation.
// M=NN (BM=128, 8 warps x 16 rows), N=OUTD, K=1088 (17 chunks of 64).
template <int OUTD, bool RELU, bool USE_X1, bool OUT_X1>
__global__ __launch_bounds__(256) void gemm_mma(const float* __restrict__ xin,
                                                const float* __restrict__ W,
                                                const float* __restrict__ rootW,
                                                const float* __restrict__ bias,
                                                float* __restrict__ outp) {
    constexpr int AP = 72;                 // f16 pitch: 144B rows, conflict-free ldmatrix
    extern __shared__ __half sm[];
    __half* Ahs = sm;                      // 128 x AP
    __half* Bh  = Ahs + 128 * AP;          // OUTD x AP
    __half* Bl  = Bh + OUTD * AP;          // OUTD x AP

    int tid = threadIdx.x;
    int wid = tid >> 5, lane = tid & 31;
    int g = lane >> 3, r = lane & 7;
    int v0 = blockIdx.x * 128;

    u32 sb = smem_u32(sm);
    // A frag rows: m = wid*16 + (g&1)*8 + r ; cols: (g>>1)*8 (+ks*16 per step)
    u32 a_base = sb + ((u32)((wid * 16 + (g & 1) * 8 + r) * AP + (g >> 1) * 8)) * 2;
    // B frag rows: n = (g>>1)*8 + r ; cols: (g&1)*8 (+ks*16 per step)
    u32 bh_base = sb + 128 * AP * 2 + ((u32)(((g >> 1) * 8 + r) * AP + (g & 1) * 8)) * 2;
    u32 bl_base = bh_base + OUTD * AP * 2;

    float acc[OUTD / 8][4];
    #pragma unroll
    for (int i = 0; i < OUTD / 8; ++i)
        #pragma unroll
        for (int j = 0; j < 4; ++j) acc[i][j] = 0.f;

    for (int t = 0; t < 17; ++t) {
        // ---- A tile prep: 128 nodes x 64 k -> fp16 (scale in fp32, one rounding) ----
        if (t < 16) {
            #pragma unroll
            for (int i = 0; i < 4; ++i) {
                int idx = tid + i * 256;      // uint4 units (8 halves), 0..1023
                int node = idx >> 3, kq = idx & 7;
                int v = v0 + node;
                uint4 yv = make_uint4(0, 0, 0, 0);
                float sc = 0.f;
                if (v < NN) {
                    yv = *(const uint4*)&g_Yh[(size_t)v * 1024 + t * 64 + kq * 8];
                    sc = g_inv[v * RR + t];
                }
                u32 yw[4] = {yv.x, yv.y, yv.z, yv.w};
                u32 ow[4];
                #pragma unroll
                for (int q = 0; q < 4; ++q) {
                    float2 f = __half22float2(*(__half2*)&yw[q]);
                    __half2 m = __floats2half2_rn(f.x * sc, f.y * sc);
                    ow[q] = *(u32*)&m;
                }
                *(uint4*)&Ahs[node * AP + kq * 8] = make_uint4(ow[0], ow[1], ow[2], ow[3]);
            }
        } else {
            // root chunk: fp32 input -> fp16
            #pragma unroll
            for (int i = 0; i < 4; ++i) {
                int idx = tid + i * 256;      // 8-float units, 0..1023
                int node = idx >> 3, kq = idx & 7;
                int v = v0 + node;
                float4 a4 = make_float4(0.f, 0.f, 0.f, 0.f);
                float4 b4 = make_float4(0.f, 0.f, 0.f, 0.f);
                if (v < NN) {
                    const float* rsrc = USE_X1 ? g_X1 : xin;
                    a4 = *(const float4*)&rsrc[(size_t)v * 64 + kq * 8];
                    b4 = *(const float4*)&rsrc[(size_t)v * 64 + kq * 8 + 4];
                }
                __half2 m0 = __floats2half2_rn(a4.x, a4.y);
                __half2 m1 = __floats2half2_rn(a4.z, a4.w);
                __half2 m2 = __floats2half2_rn(b4.x, b4.y);
                __half2 m3 = __floats2half2_rn(b4.z, b4.w);
                *(uint4*)&Ahs[node * AP + kq * 8] =
                    make_uint4(*(u32*)&m0, *(u32*)&m1, *(u32*)&m2, *(u32*)&m3);
            }
        }
        // ---- B tile prep: transpose [64 k][OUTD n] fp32 -> Bs[n][k], f16 hi/lo split ----
        {
            const float4* Bsrc = (t < 16) ? (const float4*)(W + (size_t)t * 64 * OUTD)
                                          : (const float4*)rootW;
            constexpr int NF4 = 64 * OUTD / 4;
            #pragma unroll
            for (int i = 0; i < NF4 / 256; ++i) {
                int idx = tid + i * 256;
                int k = idx / (OUTD / 4), nq = idx % (OUTD / 4);
                float4 w4 = Bsrc[idx];
                float f[4] = {w4.x, w4.y, w4.z, w4.w};
                #pragma unroll
                for (int j = 0; j < 4; ++j) {
                    int n = nq * 4 + j;
                    __half h = __float2half_rn(f[j]);
                    Bh[n * AP + k] = h;
                    Bl[n * AP + k] = __float2half_rn(f[j] - __half2float(h));
                }
            }
        }
        __syncthreads();
        // ---- MMA: 4 k-steps x (OUTD/16) n-blocks x 2 split terms ----
        #pragma unroll
        for (int ks = 0; ks < 4; ++ks) {
            u32 a[4];
            ldm4(a, a_base + ks * 32);
            #pragma unroll
            for (int nb = 0; nb < OUTD / 16; ++nb) {
                u32 bh[4], bl[4];
                ldm4(bh, bh_base + ks * 32 + nb * (16 * AP * 2));
                ldm4(bl, bl_base + ks * 32 + nb * (16 * AP * 2));
                mma16816(acc[nb * 2],     a, bh[0], bh[1]);
                mma16816(acc[nb * 2 + 1], a, bh[2], bh[3]);
                mma16816(acc[nb * 2],     a, bl[0], bl[1]);
                mma16816(acc[nb * 2 + 1], a, bl[2], bl[3]);
            }
        }
        __syncthreads();
    }

    // ---- epilogue: bias (+relu), direct fragment store ----
    float* dst = OUT_X1 ? g_X1 : outp;     // device-side symbol reference (ATS pitfall!)
    int row0 = v0 + wid * 16 + (lane >> 2);
    int colb = (lane & 3) * 2;
    #pragma unroll
    for (int ns = 0; ns < OUTD / 8; ++ns) {
        int col = ns * 8 + colb;
        float bx = bias[col], by = bias[col + 1];
        float o0 = acc[ns][0] + bx, o1 = acc[ns][1] + by;
        float o2 = acc[ns][2] + bx, o3 = acc[ns][3] + by;
        if (RELU) {
            o0 = fmaxf(o0, 0.f); o1 = fmaxf(o1, 0.f);
            o2 = fmaxf(o2, 0.f); o3 = fmaxf(o3, 0.f);
        }
        if (row0 < NN)
            *(float2*)&dst[(size_t)row0 * OUTD + col] = make_float2(o0, o1);
        if (row0 + 8 < NN)
            *(float2*)&dst[(size_t)(row0 + 8) * OUTD + col] = make_float2(o2, o3);
    }
}

// ---------------- launch ----------------
extern "C" void kernel_launch(void* const* d_in, const int* in_sizes, int n_in,
                              void* d_out, int out_size) {
    const int*   ei    = (const int*)d_in[0];
    const int*   et    = (const int*)d_in[1];
    const float* x     = (const float*)d_in[2];
    const float* W1    = (const float*)d_in[3];
    const float* root1 = (const float*)d_in[4];
    const float* b1    = (const float*)d_in[5];
    const float* W2    = (const float*)d_in[6];
    const float* root2 = (const float*)d_in[7];
    const float* b2    = (const float*)d_in[8];
    float* out = (float*)d_out;

    (void)in_sizes; (void)n_in; (void)out_size;

    constexpr int AP = 72;
    const int SMEM1 = (128 + 2 * 64) * AP * 2;   // 36864 B
    const int SMEM2 = (128 + 2 * 16) * AP * 2;   // 23040 B
    cudaFuncSetAttribute(gemm_mma<64, true, false, true>,
                         cudaFuncAttributeMaxDynamicSharedMemorySize, SMEM1);
    cudaFuncSetAttribute(gemm_mma<16, false, true, false>,
                         cudaFuncAttributeMaxDynamicSharedMemorySize, SMEM2);

    const int Z_Y_BLOCKS = (int)(((size_t)NN * RR * HH * 2 / 16 + 255) / 256); // 25000
    const int SC_BLOCKS  = (int)(((size_t)EE * 8 + 255) / 256);                // 25000
    const int GB         = (NN + 127) / 128;

    // ---- layer 1 ----
    zero_cnt_k<<<(NN * RR + 255) / 256, 256>>>();
    zero_Y_k<<<Z_Y_BLOCKS, 256>>>();
    scatter_h<false, true><<<SC_BLOCKS, 256>>>(ei, et, (const float4*)x);  // + counts
    inv_k<<<(NN * RR + 255) / 256, 256>>>();
    gemm_mma<64, true, false, true><<<GB, 256, SMEM1>>>(x, W1, root1, b1, nullptr);

    // ---- layer 2 ----
    zero_Y_k<<<Z_Y_BLOCKS, 256>>>();
    scatter_h<true, false><<<SC_BLOCKS, 256>>>(ei, et, nullptr);
    gemm_mma<16, false, true, false><<<GB, 256, SMEM2>>>(nullptr, W2, root2, b2, out);
}